// round 2
// baseline (speedup 1.0000x reference)
#include <cuda_runtime.h>
#include <math.h>

#define NN 50000
#define NE 800000
#define HID 128

// ---------- static scratch (allocation-free contract) ----------
__device__ int   g_deg[NN];
__device__ int   g_cur[NN];
__device__ float g_dis[NN];
__device__ int   g_rowptr[NN + 1];
__device__ int   g_cols[NE];
__device__ float g_wts[NE];
__device__ float g_t[(size_t)NN * HID];    // pre-aggregation (x@W)
__device__ float g_h[(size_t)NN * HID];    // post-aggregation
__device__ float g_ab[(size_t)NN * 256];   // [A | B] per node

// ---------- graph build ----------
__global__ void zero_kernel(int n) {
    int i = blockIdx.x * blockDim.x + threadIdx.x;
    if (i < n) { g_deg[i] = 0; g_cur[i] = 0; }
}

__global__ void indeg_kernel(const int* __restrict__ ei, int E) {
    int e = blockIdx.x * blockDim.x + threadIdx.x;
    if (e < E) atomicAdd(&g_deg[ei[E + e]], 1);
}

__global__ void dis_kernel(int n) {
    int i = blockIdx.x * blockDim.x + threadIdx.x;
    if (i < n) g_dis[i] = rsqrtf((float)(g_deg[i] + 1));
}

// single-block scan (exclusive prefix sum of g_deg -> g_rowptr)
__global__ void scan_kernel(int n) {
    __shared__ int wsum[32];
    int tid = threadIdx.x, lane = tid & 31, wid = tid >> 5;
    int carry = 0;
    for (int base = 0; base < n; base += 1024) {
        int i = base + tid;
        int v = (i < n) ? g_deg[i] : 0;
        int s = v;
        #pragma unroll
        for (int off = 1; off < 32; off <<= 1) {
            int t = __shfl_up_sync(0xffffffffu, s, off);
            if (lane >= off) s += t;
        }
        if (lane == 31) wsum[wid] = s;
        __syncthreads();
        if (wid == 0) {
            int ws = wsum[lane];
            #pragma unroll
            for (int off = 1; off < 32; off <<= 1) {
                int t = __shfl_up_sync(0xffffffffu, ws, off);
                if (lane >= off) ws += t;
            }
            wsum[lane] = ws;  // inclusive warp totals
        }
        __syncthreads();
        int wpre = (wid > 0) ? wsum[wid - 1] : 0;
        int incl = s + wpre;
        if (i < n) g_rowptr[i] = carry + incl - v;
        int total = wsum[31];
        __syncthreads();
        carry += total;
    }
    if (tid == 0) g_rowptr[n] = carry;
}

__global__ void fill_kernel(const int* __restrict__ ei, int E) {
    int e = blockIdx.x * blockDim.x + threadIdx.x;
    if (e >= E) return;
    int s = ei[e];
    int c = ei[E + e];
    int pos = g_rowptr[c] + atomicAdd(&g_cur[c], 1);
    g_cols[pos] = s;
    g_wts[pos] = g_dis[s] * g_dis[c];
}

// ---------- x @ W1 (N x 5 @ 5 x 128) ----------
__global__ void xw1_kernel(const float* __restrict__ x, const float* __restrict__ W1, int n) {
    __shared__ float Ws[5][HID];
    int tid = threadIdx.x;  // 128
    #pragma unroll
    for (int f = 0; f < 5; f++) Ws[f][tid] = W1[f * HID + tid];
    __syncthreads();
    int node0 = blockIdx.x * 8;
    #pragma unroll
    for (int i = 0; i < 8; i++) {
        int node = node0 + i;
        if (node >= n) break;
        float acc = 0.f;
        #pragma unroll
        for (int f = 0; f < 5; f++) acc += x[(size_t)node * 5 + f] * Ws[f][tid];
        g_t[(size_t)node * HID + tid] = acc;
    }
}

// ---------- GCN aggregation: one warp per node ----------
__global__ void agg_kernel(const float* __restrict__ bias, int n, int do_relu) {
    int gwid = (blockIdx.x * blockDim.x + threadIdx.x) >> 5;
    int lane = threadIdx.x & 31;
    if (gwid >= n) return;
    int node = gwid;
    float d = g_dis[node];
    float self = d * d;
    const float* xr = g_t + (size_t)node * HID;
    float a0 = self * xr[lane];
    float a1 = self * xr[lane + 32];
    float a2 = self * xr[lane + 64];
    float a3 = self * xr[lane + 96];
    int beg = g_rowptr[node], end = g_rowptr[node + 1];
    for (int e = beg; e < end; e++) {
        int s = __ldg(&g_cols[e]);
        float w = __ldg(&g_wts[e]);
        const float* sr = g_t + (size_t)s * HID;
        a0 += w * sr[lane];
        a1 += w * sr[lane + 32];
        a2 += w * sr[lane + 64];
        a3 += w * sr[lane + 96];
    }
    a0 += bias[lane]; a1 += bias[lane + 32]; a2 += bias[lane + 64]; a3 += bias[lane + 96];
    if (do_relu) {
        a0 = fmaxf(a0, 0.f); a1 = fmaxf(a1, 0.f); a2 = fmaxf(a2, 0.f); a3 = fmaxf(a3, 0.f);
    }
    float* orow = g_h + (size_t)node * HID;
    orow[lane] = a0; orow[lane + 32] = a1; orow[lane + 64] = a2; orow[lane + 96] = a3;
}

// ---------- dense [n,128] @ [128,128] GEMM, register-blocked ----------
// 256 threads: each computes 8 rows x 4 cols. W row-major with row stride 128.
__global__ void gemm128_kernel(const float* __restrict__ H, const float* __restrict__ W,
                               float* __restrict__ O, int ostride, int n) {
    __shared__ float Ws[32][HID];
    __shared__ float Hs[32][65];  // padded, transposed tile
    int tid = threadIdx.x;
    int cx4 = (tid & 31) * 4;   // col base
    int ry8 = (tid >> 5) * 8;   // row base (within tile)
    int row0 = blockIdx.x * 64;
    float acc[8][4];
    #pragma unroll
    for (int r = 0; r < 8; r++)
        #pragma unroll
        for (int j = 0; j < 4; j++) acc[r][j] = 0.f;

    for (int k0 = 0; k0 < HID; k0 += 32) {
        // load W chunk [32][128]
        #pragma unroll
        for (int i = 0; i < 4; i++) {
            int q = tid + i * 256;            // float4 index 0..1023
            int kk = q >> 5, cc = (q & 31) * 4;
            *(float4*)&Ws[kk][cc] = *(const float4*)&W[(size_t)(k0 + kk) * HID + cc];
        }
        // load H chunk transposed: rows row0..row0+63, cols k0..k0+31
        #pragma unroll
        for (int i = 0; i < 2; i++) {
            int q = tid + i * 256;            // float4 index 0..511
            int r = q >> 3, kq = (q & 7) * 4;
            int gr = row0 + r;
            float4 hv = make_float4(0.f, 0.f, 0.f, 0.f);
            if (gr < n) hv = *(const float4*)&H[(size_t)gr * HID + k0 + kq];
            Hs[kq + 0][r] = hv.x; Hs[kq + 1][r] = hv.y;
            Hs[kq + 2][r] = hv.z; Hs[kq + 3][r] = hv.w;
        }
        __syncthreads();
        #pragma unroll
        for (int kk = 0; kk < 32; kk++) {
            float4 wv = *(float4*)&Ws[kk][cx4];
            float hv[8];
            #pragma unroll
            for (int r = 0; r < 8; r++) hv[r] = Hs[kk][ry8 + r];
            #pragma unroll
            for (int r = 0; r < 8; r++) {
                acc[r][0] += hv[r] * wv.x;
                acc[r][1] += hv[r] * wv.y;
                acc[r][2] += hv[r] * wv.z;
                acc[r][3] += hv[r] * wv.w;
            }
        }
        __syncthreads();
    }
    #pragma unroll
    for (int r = 0; r < 8; r++) {
        int gr = row0 + ry8 + r;
        if (gr < n) {
            float4 o = make_float4(acc[r][0], acc[r][1], acc[r][2], acc[r][3]);
            *(float4*)&O[(size_t)gr * ostride + cx4] = o;
        }
    }
}

// ---------- per-edge MLP head: one warp per edge ----------
__global__ void edge_kernel(const int* __restrict__ ei, const float* __restrict__ ea,
                            const float* __restrict__ WmE,   // Wm1 rows 256..259
                            const float* __restrict__ bm1, const float* __restrict__ Wm2,
                            const float* __restrict__ bm2, float* __restrict__ out, int E) {
    __shared__ float sWe[4][HID];
    __shared__ float sb[HID];
    __shared__ float sw2[HID];
    int tid = threadIdx.x;  // 256
    for (int i = tid; i < 4 * HID; i += 256) sWe[i >> 7][i & 127] = WmE[i];
    for (int i = tid; i < HID; i += 256) { sb[i] = bm1[i]; sw2[i] = Wm2[i]; }
    __syncthreads();
    int lane = tid & 31, w = tid >> 5;
    int e = blockIdx.x * 8 + w;
    if (e >= E) return;
    int s = ei[e];
    int d = ei[E + e];
    float e0 = ea[(size_t)e * 4 + 0], e1 = ea[(size_t)e * 4 + 1];
    float e2 = ea[(size_t)e * 4 + 2], e3 = ea[(size_t)e * 4 + 3];
    const float* Ar = g_ab + (size_t)s * 256;
    const float* Br = g_ab + (size_t)d * 256 + HID;
    float partial = 0.f;
    #pragma unroll
    for (int j = 0; j < 4; j++) {
        int k = lane + j * 32;
        float z = Ar[k] + Br[k] + sb[k]
                + e0 * sWe[0][k] + e1 * sWe[1][k] + e2 * sWe[2][k] + e3 * sWe[3][k];
        z = fmaxf(z, 0.f);
        partial += z * sw2[k];
    }
    #pragma unroll
    for (int off = 16; off; off >>= 1)
        partial += __shfl_xor_sync(0xffffffffu, partial, off);
    if (lane == 0) {
        float v = partial + bm2[0];
        out[e] = 1.f / (1.f + expf(-v));
    }
}

// ---------- launcher ----------
extern "C" void kernel_launch(void* const* d_in, const int* in_sizes, int n_in,
                              void* d_out, int out_size) {
    const float* x    = (const float*)d_in[0];
    const float* ea   = (const float*)d_in[1];
    const float* W1   = (const float*)d_in[2];
    const float* b1   = (const float*)d_in[3];
    const float* W2   = (const float*)d_in[4];
    const float* b2   = (const float*)d_in[5];
    const float* Wm1  = (const float*)d_in[6];
    const float* bm1  = (const float*)d_in[7];
    const float* Wm2  = (const float*)d_in[8];
    const float* bm2  = (const float*)d_in[9];
    const int*   ei   = (const int*)d_in[10];   // int32! (JAX x64 disabled)
    float* out = (float*)d_out;

    int n = in_sizes[0] / 5;          // 50000
    int E = in_sizes[10] / 2;         // 800000

    float *p_t, *p_h, *p_ab;
    cudaGetSymbolAddress((void**)&p_t, g_t);
    cudaGetSymbolAddress((void**)&p_h, g_h);
    cudaGetSymbolAddress((void**)&p_ab, g_ab);

    // graph build
    zero_kernel<<<(n + 255) / 256, 256>>>(n);
    indeg_kernel<<<(E + 255) / 256, 256>>>(ei, E);
    dis_kernel<<<(n + 255) / 256, 256>>>(n);
    scan_kernel<<<1, 1024>>>(n);
    fill_kernel<<<(E + 255) / 256, 256>>>(ei, E);

    // layer 1: t = x@W1 ; h = relu(agg(t) + b1)
    xw1_kernel<<<(n + 7) / 8, 128>>>(x, W1, n);
    agg_kernel<<<(n * 32 + 255) / 256, 256>>>(b1, n, 1);

    // layer 2: t = h@W2 ; h = agg(t) + b2
    gemm128_kernel<<<(n + 63) / 64, 256>>>(p_h, W2, p_t, HID, n);
    agg_kernel<<<(n * 32 + 255) / 256, 256>>>(b2, n, 0);

    // node projections A = h@Wm1[0:128], B = h@Wm1[128:256]
    gemm128_kernel<<<(n + 63) / 64, 256>>>(p_h, Wm1, p_ab, 256, n);
    gemm128_kernel<<<(n + 63) / 64, 256>>>(p_h, Wm1 + 128 * HID, p_ab + HID, 256, n);

    // per-edge head
    edge_kernel<<<(E + 7) / 8, 256>>>(ei, ea, Wm1 + 256 * HID, bm1, Wm2, bm2, out, E);
}

// round 3
// speedup vs baseline: 1.0543x; 1.0543x over previous
#include <cuda_runtime.h>
#include <math.h>

#define NN 50000
#define NE 800000
#define HID 128
#define NB 196   // ceil(50000/256)

// ---------- static scratch (allocation-free contract) ----------
struct __align__(8) CsrEnt { int c; float w; };
__device__ int    g_deg[NN];
__device__ int    g_cur[NN];
__device__ float  g_dis[NN];
__device__ int    g_rowptr[NN + 1];
__device__ CsrEnt g_csr[NE];
__device__ int    g_bsum[256];
__device__ int    g_boff[256];
__device__ float  g_t[(size_t)NN * HID];    // pre-aggregation (x@W)
__device__ float  g_h[(size_t)NN * HID];    // post-aggregation
__device__ float  g_ab[(size_t)NN * 256];   // [A | B] per node

// ---------- f32x2 packed FMA (PTX-only; exact fp32 semantics) ----------
__device__ __forceinline__ unsigned long long ffma2(unsigned long long a,
                                                    unsigned long long b,
                                                    unsigned long long c) {
    unsigned long long d;
    asm("fma.rn.f32x2 %0, %1, %2, %3;" : "=l"(d) : "l"(a), "l"(b), "l"(c));
    return d;
}

// ---------- graph build ----------
__global__ void indeg_kernel(const int* __restrict__ ei, int E) {
    int e = blockIdx.x * blockDim.x + threadIdx.x;
    if (e < E) atomicAdd(&g_deg[ei[E + e]], 1);
}

__global__ void dis_kernel(int n) {
    int i = blockIdx.x * blockDim.x + threadIdx.x;
    if (i < n) g_dis[i] = rsqrtf((float)(g_deg[i] + 1));
}

// per-block sums of g_deg
__global__ void bsum_kernel(int n) {
    __shared__ int sm[8];
    int b = blockIdx.x;
    int i = b * 256 + threadIdx.x;
    int v = (i < n) ? g_deg[i] : 0;
    int lane = threadIdx.x & 31, wid = threadIdx.x >> 5;
    #pragma unroll
    for (int off = 16; off; off >>= 1) v += __shfl_xor_sync(0xffffffffu, v, off);
    if (lane == 0) sm[wid] = v;
    __syncthreads();
    if (wid == 0) {
        int t = (lane < 8) ? sm[lane] : 0;
        #pragma unroll
        for (int off = 4; off; off >>= 1) t += __shfl_xor_sync(0xffffffffu, t, off);
        if (lane == 0) g_bsum[b] = t;
    }
}

// exclusive scan of block sums (single block of 256; NB <= 256)
__global__ void bscan_kernel(int nb, int n) {
    __shared__ int wsum[8];
    int tid = threadIdx.x, lane = tid & 31, wid = tid >> 5;
    int v = (tid < nb) ? g_bsum[tid] : 0;
    int s = v;
    #pragma unroll
    for (int off = 1; off < 32; off <<= 1) {
        int t = __shfl_up_sync(0xffffffffu, s, off);
        if (lane >= off) s += t;
    }
    if (lane == 31) wsum[wid] = s;
    __syncthreads();
    if (wid == 0 && lane < 8) {
        int ws = wsum[lane];
        #pragma unroll
        for (int off = 1; off < 8; off <<= 1) {
            int t = __shfl_up_sync(0xffu, ws, off);
            if (lane >= off) ws += t;
        }
        wsum[lane] = ws;
    }
    __syncthreads();
    int incl = s + ((wid > 0) ? wsum[wid - 1] : 0);
    if (tid < nb) g_boff[tid] = incl - v;
    if (tid == nb - 1) g_rowptr[n] = incl;
}

// per-block exclusive scan + block offset -> rowptr
__global__ void rowptr_kernel(int n) {
    __shared__ int wsum[8];
    int b = blockIdx.x;
    int i = b * 256 + threadIdx.x;
    int tid = threadIdx.x, lane = tid & 31, wid = tid >> 5;
    int v = (i < n) ? g_deg[i] : 0;
    int s = v;
    #pragma unroll
    for (int off = 1; off < 32; off <<= 1) {
        int t = __shfl_up_sync(0xffffffffu, s, off);
        if (lane >= off) s += t;
    }
    if (lane == 31) wsum[wid] = s;
    __syncthreads();
    if (wid == 0 && lane < 8) {
        int ws = wsum[lane];
        #pragma unroll
        for (int off = 1; off < 8; off <<= 1) {
            int t = __shfl_up_sync(0xffu, ws, off);
            if (lane >= off) ws += t;
        }
        wsum[lane] = ws;
    }
    __syncthreads();
    int excl = s - v + ((wid > 0) ? wsum[wid - 1] : 0);
    if (i < n) g_rowptr[i] = g_boff[b] + excl;
}

__global__ void fill_kernel(const int* __restrict__ ei, int E) {
    int e = blockIdx.x * blockDim.x + threadIdx.x;
    if (e >= E) return;
    int s = ei[e];
    int c = ei[E + e];
    int pos = g_rowptr[c] + atomicAdd(&g_cur[c], 1);
    CsrEnt en; en.c = s; en.w = g_dis[s] * g_dis[c];
    g_csr[pos] = en;
}

// ---------- x @ W1 (N x 5 @ 5 x 128) ----------
__global__ void xw1_kernel(const float* __restrict__ x, const float* __restrict__ W1, int n) {
    __shared__ float Ws[5][HID];
    int tid = threadIdx.x;  // 128
    #pragma unroll
    for (int f = 0; f < 5; f++) Ws[f][tid] = W1[f * HID + tid];
    __syncthreads();
    int node0 = blockIdx.x * 8;
    #pragma unroll
    for (int i = 0; i < 8; i++) {
        int node = node0 + i;
        if (node >= n) break;
        float acc = 0.f;
        #pragma unroll
        for (int f = 0; f < 5; f++) acc += x[(size_t)node * 5 + f] * Ws[f][tid];
        g_t[(size_t)node * HID + tid] = acc;
    }
}

// ---------- GCN aggregation: one warp per node ----------
__global__ void agg_kernel(const float* __restrict__ bias, int n, int do_relu) {
    int gwid = (blockIdx.x * blockDim.x + threadIdx.x) >> 5;
    int lane = threadIdx.x & 31;
    if (gwid >= n) return;
    int node = gwid;
    float d = g_dis[node];
    float self = d * d;
    const float* xr = g_t + (size_t)node * HID;
    float a0 = self * xr[lane];
    float a1 = self * xr[lane + 32];
    float a2 = self * xr[lane + 64];
    float a3 = self * xr[lane + 96];
    int beg = g_rowptr[node], end = g_rowptr[node + 1];
    for (int e = beg; e < end; e++) {
        unsigned long long raw = __ldg((const unsigned long long*)&g_csr[e]);
        CsrEnt en = *(CsrEnt*)&raw;
        const float* sr = g_t + (size_t)en.c * HID;
        a0 += en.w * sr[lane];
        a1 += en.w * sr[lane + 32];
        a2 += en.w * sr[lane + 64];
        a3 += en.w * sr[lane + 96];
    }
    a0 += bias[lane]; a1 += bias[lane + 32]; a2 += bias[lane + 64]; a3 += bias[lane + 96];
    if (do_relu) {
        a0 = fmaxf(a0, 0.f); a1 = fmaxf(a1, 0.f); a2 = fmaxf(a2, 0.f); a3 = fmaxf(a3, 0.f);
    }
    float* orow = g_h + (size_t)node * HID;
    orow[lane] = a0; orow[lane + 32] = a1; orow[lane + 64] = a2; orow[lane + 96] = a3;
}

// ---------- dense [n,128] @ [128,128] GEMM with packed f32x2 FMA ----------
// 256 threads: each computes 8 rows x 4 cols (as 2 f32x2 accumulators per row).
__global__ void gemm128_kernel(const float* __restrict__ H, const float* __restrict__ W,
                               float* __restrict__ O, int ostride, int n) {
    __shared__ float4 Ws4[32][32];     // [kk][col/4]   16 KB
    __shared__ float2 Hs2[32][65];     // [kk][row] duplicated (h,h)  ~16.6 KB
    int tid = threadIdx.x;
    int c4  = tid & 31;        // float4 column index (cols c4*4 .. c4*4+3)
    int r0  = (tid >> 5) * 8;  // row base within tile
    int row0 = blockIdx.x * 64;

    unsigned long long acc[8][2];
    #pragma unroll
    for (int r = 0; r < 8; r++) { acc[r][0] = 0ull; acc[r][1] = 0ull; }

    for (int k0 = 0; k0 < HID; k0 += 32) {
        // W chunk [32][128]
        #pragma unroll
        for (int i = 0; i < 4; i++) {
            int q = tid + i * 256;            // 0..1023 float4 slots
            int kk = q >> 5, cc = q & 31;
            Ws4[kk][cc] = *(const float4*)&W[(size_t)(k0 + kk) * HID + cc * 4];
        }
        // H chunk, duplicated pairs: rows row0..row0+63, cols k0..k0+31
        #pragma unroll
        for (int i = 0; i < 2; i++) {
            int q = tid + i * 256;            // 0..511 float4 slots
            int r = q >> 3, kq = (q & 7) * 4;
            int gr = row0 + r;
            float4 hv = make_float4(0.f, 0.f, 0.f, 0.f);
            if (gr < n) hv = *(const float4*)&H[(size_t)gr * HID + k0 + kq];
            Hs2[kq + 0][r] = make_float2(hv.x, hv.x);
            Hs2[kq + 1][r] = make_float2(hv.y, hv.y);
            Hs2[kq + 2][r] = make_float2(hv.z, hv.z);
            Hs2[kq + 3][r] = make_float2(hv.w, hv.w);
        }
        __syncthreads();
        #pragma unroll
        for (int kk = 0; kk < 32; kk++) {
            ulonglong2 wv = *(ulonglong2*)&Ws4[kk][c4];   // LDS.128: (w0,w1)|(w2,w3)
            #pragma unroll
            for (int r = 0; r < 8; r++) {
                unsigned long long h2 = *(unsigned long long*)&Hs2[kk][r0 + r]; // broadcast
                acc[r][0] = ffma2(h2, wv.x, acc[r][0]);
                acc[r][1] = ffma2(h2, wv.y, acc[r][1]);
            }
        }
        __syncthreads();
    }
    #pragma unroll
    for (int r = 0; r < 8; r++) {
        int gr = row0 + r0 + r;
        if (gr < n) {
            float2 lo = *(float2*)&acc[r][0];
            float2 hi = *(float2*)&acc[r][1];
            float4 o = make_float4(lo.x, lo.y, hi.x, hi.y);
            *(float4*)&O[(size_t)gr * ostride + c4 * 4] = o;
        }
    }
}

// ---------- per-edge MLP head: one warp per edge, float4 everywhere ----------
__global__ void edge_kernel(const int* __restrict__ ei, const float* __restrict__ ea,
                            const float* __restrict__ WmE,   // Wm1 rows 256..259
                            const float* __restrict__ bm1, const float* __restrict__ Wm2,
                            const float* __restrict__ bm2, float* __restrict__ out, int E) {
    __shared__ float4 sWe[4][32];
    __shared__ float4 sb4[32];
    __shared__ float4 sw24[32];
    int tid = threadIdx.x;  // 256
    if (tid < 128) sWe[tid >> 5][tid & 31] = *(const float4*)&WmE[(tid >> 5) * HID + (tid & 31) * 4];
    else if (tid < 160) sb4[tid - 128] = *(const float4*)&bm1[(tid - 128) * 4];
    else if (tid < 192) sw24[tid - 160] = *(const float4*)&Wm2[(tid - 160) * 4];
    __syncthreads();
    int lane = tid & 31, w = tid >> 5;
    int e = blockIdx.x * 8 + w;
    if (e >= E) return;
    int s = ei[e];
    int d = ei[E + e];
    float4 eav = *(const float4*)&ea[(size_t)e * 4];    // warp-broadcast 16B
    float4 A = *(const float4*)&g_ab[(size_t)s * 256 + lane * 4];
    float4 B = *(const float4*)&g_ab[(size_t)d * 256 + HID + lane * 4];
    float4 b = sb4[lane];
    float4 w0 = sWe[0][lane], w1 = sWe[1][lane], w2 = sWe[2][lane], w3 = sWe[3][lane];
    float4 z;
    z.x = A.x + B.x + b.x + eav.x * w0.x + eav.y * w1.x + eav.z * w2.x + eav.w * w3.x;
    z.y = A.y + B.y + b.y + eav.x * w0.y + eav.y * w1.y + eav.z * w2.y + eav.w * w3.y;
    z.z = A.z + B.z + b.z + eav.x * w0.z + eav.y * w1.z + eav.z * w2.z + eav.w * w3.z;
    z.w = A.w + B.w + b.w + eav.x * w0.w + eav.y * w1.w + eav.z * w2.w + eav.w * w3.w;
    float4 v2 = sw24[lane];
    float partial = fmaxf(z.x, 0.f) * v2.x + fmaxf(z.y, 0.f) * v2.y
                  + fmaxf(z.z, 0.f) * v2.z + fmaxf(z.w, 0.f) * v2.w;
    #pragma unroll
    for (int off = 16; off; off >>= 1)
        partial += __shfl_xor_sync(0xffffffffu, partial, off);
    if (lane == 0) {
        float v = partial + bm2[0];
        out[e] = 1.f / (1.f + expf(-v));
    }
}

// ---------- launcher ----------
extern "C" void kernel_launch(void* const* d_in, const int* in_sizes, int n_in,
                              void* d_out, int out_size) {
    const float* x    = (const float*)d_in[0];
    const float* ea   = (const float*)d_in[1];
    const float* W1   = (const float*)d_in[2];
    const float* b1   = (const float*)d_in[3];
    const float* W2   = (const float*)d_in[4];
    const float* b2   = (const float*)d_in[5];
    const float* Wm1  = (const float*)d_in[6];
    const float* bm1  = (const float*)d_in[7];
    const float* Wm2  = (const float*)d_in[8];
    const float* bm2  = (const float*)d_in[9];
    const int*   ei   = (const int*)d_in[10];   // int32 (JAX x64 disabled)
    float* out = (float*)d_out;

    int n = in_sizes[0] / 5;          // 50000
    int E = in_sizes[10] / 2;         // 800000
    int nb = (n + 255) / 256;         // 196

    void *p_deg, *p_cur;
    float *p_t, *p_h, *p_ab;
    cudaGetSymbolAddress(&p_deg, g_deg);
    cudaGetSymbolAddress(&p_cur, g_cur);
    cudaGetSymbolAddress((void**)&p_t, g_t);
    cudaGetSymbolAddress((void**)&p_h, g_h);
    cudaGetSymbolAddress((void**)&p_ab, g_ab);

    // graph build
    cudaMemsetAsync(p_deg, 0, (size_t)n * sizeof(int), 0);
    cudaMemsetAsync(p_cur, 0, (size_t)n * sizeof(int), 0);
    indeg_kernel<<<(E + 255) / 256, 256>>>(ei, E);
    dis_kernel<<<(n + 255) / 256, 256>>>(n);
    bsum_kernel<<<nb, 256>>>(n);
    bscan_kernel<<<1, 256>>>(nb, n);
    rowptr_kernel<<<nb, 256>>>(n);
    fill_kernel<<<(E + 255) / 256, 256>>>(ei, E);

    // layer 1: t = x@W1 ; h = relu(agg(t) + b1)
    xw1_kernel<<<(n + 7) / 8, 128>>>(x, W1, n);
    agg_kernel<<<(n * 32 + 255) / 256, 256>>>(b1, n, 1);

    // layer 2: t = h@W2 ; h = agg(t) + b2
    gemm128_kernel<<<(n + 63) / 64, 256>>>(p_h, W2, p_t, HID, n);
    agg_kernel<<<(n * 32 + 255) / 256, 256>>>(b2, n, 0);

    // node projections A = h@Wm1[0:128], B = h@Wm1[128:256]
    gemm128_kernel<<<(n + 63) / 64, 256>>>(p_h, Wm1, p_ab, 256, n);
    gemm128_kernel<<<(n + 63) / 64, 256>>>(p_h, Wm1 + 128 * HID, p_ab + HID, 256, n);

    // per-edge head
    edge_kernel<<<(E + 7) / 8, 256>>>(ei, ea, Wm1 + 256 * HID, bm1, Wm2, bm2, out, E);
}

// round 4
// speedup vs baseline: 1.1944x; 1.1329x over previous
#include <cuda_runtime.h>
#include <math.h>

#define NN 50000
#define NE 800000
#define HID 128

// ---------- static scratch (allocation-free contract) ----------
struct __align__(8) CsrEnt { int c; float w; };
__device__ int    g_deg[NN];
__device__ int    g_cur[NN];
__device__ float  g_dis[NN];
__device__ int    g_rowptr[NN + 1];
__device__ CsrEnt g_csr[NE];
__device__ int    g_bsum[256];
__device__ int    g_boff[256];
__device__ float  g_t[(size_t)NN * HID];    // u1 [n,5] then u2 [n,128]
__device__ float  g_h[(size_t)NN * HID];    // h1 [n,128]
__device__ float  g_ab[(size_t)NN * 256];   // [A | B] per node
__device__ float  g_w2ab[128 * 256];        // W2 @ [W_A | W_B]
__device__ float  g_bab[256];               // b2 @ [W_A | W_B]

// ---------- f32x2 packed FMA (PTX-only; exact fp32 semantics) ----------
__device__ __forceinline__ unsigned long long ffma2(unsigned long long a,
                                                    unsigned long long b,
                                                    unsigned long long c) {
    unsigned long long d;
    asm("fma.rn.f32x2 %0, %1, %2, %3;" : "=l"(d) : "l"(a), "l"(b), "l"(c));
    return d;
}

// ---------- graph build ----------
__global__ void indeg_kernel(const int* __restrict__ ei, int E) {
    int e = blockIdx.x * blockDim.x + threadIdx.x;
    if (e < E) atomicAdd(&g_deg[ei[E + e]], 1);
}

__global__ void dis_kernel(int n) {
    int i = blockIdx.x * blockDim.x + threadIdx.x;
    if (i < n) g_dis[i] = rsqrtf((float)(g_deg[i] + 1));
}

__global__ void bsum_kernel(int n) {
    __shared__ int sm[8];
    int b = blockIdx.x;
    int i = b * 256 + threadIdx.x;
    int v = (i < n) ? g_deg[i] : 0;
    int lane = threadIdx.x & 31, wid = threadIdx.x >> 5;
    #pragma unroll
    for (int off = 16; off; off >>= 1) v += __shfl_xor_sync(0xffffffffu, v, off);
    if (lane == 0) sm[wid] = v;
    __syncthreads();
    if (wid == 0) {
        int t = (lane < 8) ? sm[lane] : 0;
        #pragma unroll
        for (int off = 4; off; off >>= 1) t += __shfl_xor_sync(0xffffffffu, t, off);
        if (lane == 0) g_bsum[b] = t;
    }
}

__global__ void bscan_kernel(int nb, int n) {
    __shared__ int wsum[8];
    int tid = threadIdx.x, lane = tid & 31, wid = tid >> 5;
    int v = (tid < nb) ? g_bsum[tid] : 0;
    int s = v;
    #pragma unroll
    for (int off = 1; off < 32; off <<= 1) {
        int t = __shfl_up_sync(0xffffffffu, s, off);
        if (lane >= off) s += t;
    }
    if (lane == 31) wsum[wid] = s;
    __syncthreads();
    if (wid == 0 && lane < 8) {
        int ws = wsum[lane];
        #pragma unroll
        for (int off = 1; off < 8; off <<= 1) {
            int t = __shfl_up_sync(0xffu, ws, off);
            if (lane >= off) ws += t;
        }
        wsum[lane] = ws;
    }
    __syncthreads();
    int incl = s + ((wid > 0) ? wsum[wid - 1] : 0);
    if (tid < nb) g_boff[tid] = incl - v;
    if (tid == nb - 1) g_rowptr[n] = incl;
}

__global__ void rowptr_kernel(int n) {
    __shared__ int wsum[8];
    int b = blockIdx.x;
    int i = b * 256 + threadIdx.x;
    int tid = threadIdx.x, lane = tid & 31, wid = tid >> 5;
    int v = (i < n) ? g_deg[i] : 0;
    int s = v;
    #pragma unroll
    for (int off = 1; off < 32; off <<= 1) {
        int t = __shfl_up_sync(0xffffffffu, s, off);
        if (lane >= off) s += t;
    }
    if (lane == 31) wsum[wid] = s;
    __syncthreads();
    if (wid == 0 && lane < 8) {
        int ws = wsum[lane];
        #pragma unroll
        for (int off = 1; off < 8; off <<= 1) {
            int t = __shfl_up_sync(0xffu, ws, off);
            if (lane >= off) ws += t;
        }
        wsum[lane] = ws;
    }
    __syncthreads();
    int excl = s - v + ((wid > 0) ? wsum[wid - 1] : 0);
    if (i < n) g_rowptr[i] = g_boff[b] + excl;
}

__global__ void fill_kernel(const int* __restrict__ ei, int E) {
    int e = blockIdx.x * blockDim.x + threadIdx.x;
    if (e >= E) return;
    int s = ei[e];
    int c = ei[E + e];
    int pos = g_rowptr[c] + atomicAdd(&g_cur[c], 1);
    CsrEnt en; en.c = s; en.w = g_dis[s] * g_dis[c];
    g_csr[pos] = en;
}

// ---------- combined weights: W2AB = W2 @ [W_A | W_B] ----------
__global__ void wcomb_kernel(const float* __restrict__ W2, const float* __restrict__ Wm1) {
    __shared__ float w2row[128];
    int k = blockIdx.x;       // 0..127 output row
    int j = threadIdx.x;      // 0..255 output col
    if (j < 128) w2row[j] = W2[k * 128 + j];
    __syncthreads();
    const float* base = (j < 128) ? (Wm1 + j) : (Wm1 + 128 * 128 + (j - 128));
    float acc = 0.f;
    #pragma unroll 8
    for (int q = 0; q < 128; q++) acc += w2row[q] * base[(size_t)q * 128];
    g_w2ab[k * 256 + j] = acc;
}

__global__ void wbias_kernel(const float* __restrict__ b2, const float* __restrict__ Wm1) {
    int j = threadIdx.x;      // 0..255
    const float* base = (j < 128) ? (Wm1 + j) : (Wm1 + 128 * 128 + (j - 128));
    float acc = 0.f;
    #pragma unroll 8
    for (int k = 0; k < 128; k++) acc += b2[k] * base[(size_t)k * 128];
    g_bab[j] = acc;
}

// ---------- layer-1 aggregation on RAW 5-dim features (agg commutes with @W1) ----------
// one warp per node, lane per edge
__global__ void aggx_kernel(const float* __restrict__ x, int n) {
    int gwid = (blockIdx.x * blockDim.x + threadIdx.x) >> 5;
    int lane = threadIdx.x & 31;
    if (gwid >= n) return;
    int node = gwid;
    int beg = g_rowptr[node], end = g_rowptr[node + 1];
    float s0 = 0.f, s1 = 0.f, s2 = 0.f, s3 = 0.f, s4 = 0.f;
    for (int e = beg + lane; e < end; e += 32) {
        unsigned long long raw = __ldg((const unsigned long long*)&g_csr[e]);
        CsrEnt en = *(CsrEnt*)&raw;
        const float* xr = x + (size_t)en.c * 5;
        s0 += en.w * xr[0]; s1 += en.w * xr[1]; s2 += en.w * xr[2];
        s3 += en.w * xr[3]; s4 += en.w * xr[4];
    }
    #pragma unroll
    for (int off = 16; off; off >>= 1) {
        s0 += __shfl_xor_sync(0xffffffffu, s0, off);
        s1 += __shfl_xor_sync(0xffffffffu, s1, off);
        s2 += __shfl_xor_sync(0xffffffffu, s2, off);
        s3 += __shfl_xor_sync(0xffffffffu, s3, off);
        s4 += __shfl_xor_sync(0xffffffffu, s4, off);
    }
    if (lane == 0) {
        float d = g_dis[node];
        float self = d * d;
        const float* xn = x + (size_t)node * 5;
        float* o = g_t + (size_t)node * 5;
        o[0] = s0 + self * xn[0];
        o[1] = s1 + self * xn[1];
        o[2] = s2 + self * xn[2];
        o[3] = s3 + self * xn[3];
        o[4] = s4 + self * xn[4];
    }
}

// ---------- h1 = relu(u1 @ W1 + b1)  (N x 5 @ 5 x 128) ----------
__global__ void gemm1_kernel(const float* __restrict__ W1, const float* __restrict__ b1, int n) {
    __shared__ float Ws[5][HID];
    __shared__ float bs[HID];
    int tid = threadIdx.x;  // 128
    #pragma unroll
    for (int f = 0; f < 5; f++) Ws[f][tid] = W1[f * HID + tid];
    bs[tid] = b1[tid];
    __syncthreads();
    int node0 = blockIdx.x * 8;
    #pragma unroll
    for (int i = 0; i < 8; i++) {
        int node = node0 + i;
        if (node >= n) break;
        const float* u = g_t + (size_t)node * 5;
        float acc = bs[tid];
        #pragma unroll
        for (int f = 0; f < 5; f++) acc += u[f] * Ws[f][tid];
        g_h[(size_t)node * HID + tid] = fmaxf(acc, 0.f);
    }
}

// ---------- layer-2 aggregation: u2 = agg(h1), float4 rows ----------
__global__ void agg2_kernel(int n) {
    int gwid = (blockIdx.x * blockDim.x + threadIdx.x) >> 5;
    int lane = threadIdx.x & 31;
    if (gwid >= n) return;
    int node = gwid;
    float d = g_dis[node];
    float self = d * d;
    float4 hv = *((const float4*)(g_h + (size_t)node * HID) + lane);
    float4 acc = make_float4(self * hv.x, self * hv.y, self * hv.z, self * hv.w);
    int beg = g_rowptr[node], end = g_rowptr[node + 1];
    int e = beg;
    for (; e + 1 < end; e += 2) {
        unsigned long long r0 = __ldg((const unsigned long long*)&g_csr[e]);
        unsigned long long r1 = __ldg((const unsigned long long*)&g_csr[e + 1]);
        CsrEnt e0 = *(CsrEnt*)&r0;
        CsrEnt e1 = *(CsrEnt*)&r1;
        float4 v0 = __ldg((const float4*)(g_h + (size_t)e0.c * HID) + lane);
        float4 v1 = __ldg((const float4*)(g_h + (size_t)e1.c * HID) + lane);
        acc.x += e0.w * v0.x; acc.y += e0.w * v0.y; acc.z += e0.w * v0.z; acc.w += e0.w * v0.w;
        acc.x += e1.w * v1.x; acc.y += e1.w * v1.y; acc.z += e1.w * v1.z; acc.w += e1.w * v1.w;
    }
    if (e < end) {
        unsigned long long r0 = __ldg((const unsigned long long*)&g_csr[e]);
        CsrEnt e0 = *(CsrEnt*)&r0;
        float4 v0 = __ldg((const float4*)(g_h + (size_t)e0.c * HID) + lane);
        acc.x += e0.w * v0.x; acc.y += e0.w * v0.y; acc.z += e0.w * v0.z; acc.w += e0.w * v0.w;
    }
    *((float4*)(g_t + (size_t)node * HID) + lane) = acc;
}

// ---------- dense [n,128] @ [128,128] GEMM (packed f32x2) + bias ----------
__global__ void gemm128_kernel(const float* __restrict__ H, const float* __restrict__ W,
                               int wstride, const float* __restrict__ bias,
                               float* __restrict__ O, int ostride, int n) {
    __shared__ float4 Ws4[32][32];
    __shared__ float2 Hs2[32][65];
    int tid = threadIdx.x;
    int c4  = tid & 31;
    int r0  = (tid >> 5) * 8;
    int row0 = blockIdx.x * 64;

    unsigned long long acc[8][2];
    #pragma unroll
    for (int r = 0; r < 8; r++) { acc[r][0] = 0ull; acc[r][1] = 0ull; }

    for (int k0 = 0; k0 < HID; k0 += 32) {
        #pragma unroll
        for (int i = 0; i < 4; i++) {
            int q = tid + i * 256;
            int kk = q >> 5, cc = q & 31;
            Ws4[kk][cc] = *(const float4*)&W[(size_t)(k0 + kk) * wstride + cc * 4];
        }
        #pragma unroll
        for (int i = 0; i < 2; i++) {
            int q = tid + i * 256;
            int r = q >> 3, kq = (q & 7) * 4;
            int gr = row0 + r;
            float4 hv = make_float4(0.f, 0.f, 0.f, 0.f);
            if (gr < n) hv = *(const float4*)&H[(size_t)gr * HID + k0 + kq];
            Hs2[kq + 0][r] = make_float2(hv.x, hv.x);
            Hs2[kq + 1][r] = make_float2(hv.y, hv.y);
            Hs2[kq + 2][r] = make_float2(hv.z, hv.z);
            Hs2[kq + 3][r] = make_float2(hv.w, hv.w);
        }
        __syncthreads();
        #pragma unroll
        for (int kk = 0; kk < 32; kk++) {
            ulonglong2 wv = *(ulonglong2*)&Ws4[kk][c4];
            #pragma unroll
            for (int r = 0; r < 8; r++) {
                unsigned long long h2 = *(unsigned long long*)&Hs2[kk][r0 + r];
                acc[r][0] = ffma2(h2, wv.x, acc[r][0]);
                acc[r][1] = ffma2(h2, wv.y, acc[r][1]);
            }
        }
        __syncthreads();
    }
    float4 bv = *(const float4*)&bias[c4 * 4];
    #pragma unroll
    for (int r = 0; r < 8; r++) {
        int gr = row0 + r0 + r;
        if (gr < n) {
            float2 lo = *(float2*)&acc[r][0];
            float2 hi = *(float2*)&acc[r][1];
            float4 o = make_float4(lo.x + bv.x, lo.y + bv.y, hi.x + bv.z, hi.y + bv.w);
            *(float4*)&O[(size_t)gr * ostride + c4 * 4] = o;
        }
    }
}

// ---------- per-edge MLP head: one warp per edge ----------
__global__ void edge_kernel(const int* __restrict__ ei, const float* __restrict__ ea,
                            const float* __restrict__ WmE,
                            const float* __restrict__ bm1, const float* __restrict__ Wm2,
                            const float* __restrict__ bm2, float* __restrict__ out, int E) {
    __shared__ float4 sWe[4][32];
    __shared__ float4 sb4[32];
    __shared__ float4 sw24[32];
    int tid = threadIdx.x;  // 256
    if (tid < 128) sWe[tid >> 5][tid & 31] = *(const float4*)&WmE[(tid >> 5) * HID + (tid & 31) * 4];
    else if (tid < 160) sb4[tid - 128] = *(const float4*)&bm1[(tid - 128) * 4];
    else if (tid < 192) sw24[tid - 160] = *(const float4*)&Wm2[(tid - 160) * 4];
    __syncthreads();
    int lane = tid & 31, w = tid >> 5;
    int e = blockIdx.x * 8 + w;
    if (e >= E) return;
    int s = ei[e];
    int d = ei[E + e];
    float4 eav = *(const float4*)&ea[(size_t)e * 4];
    float4 A = *(const float4*)&g_ab[(size_t)s * 256 + lane * 4];
    float4 B = *(const float4*)&g_ab[(size_t)d * 256 + HID + lane * 4];
    float4 b = sb4[lane];
    float4 w0 = sWe[0][lane], w1 = sWe[1][lane], w2 = sWe[2][lane], w3 = sWe[3][lane];
    float4 z;
    z.x = A.x + B.x + b.x + eav.x * w0.x + eav.y * w1.x + eav.z * w2.x + eav.w * w3.x;
    z.y = A.y + B.y + b.y + eav.x * w0.y + eav.y * w1.y + eav.z * w2.y + eav.w * w3.y;
    z.z = A.z + B.z + b.z + eav.x * w0.z + eav.y * w1.z + eav.z * w2.z + eav.w * w3.z;
    z.w = A.w + B.w + b.w + eav.x * w0.w + eav.y * w1.w + eav.z * w2.w + eav.w * w3.w;
    float4 v2 = sw24[lane];
    float partial = fmaxf(z.x, 0.f) * v2.x + fmaxf(z.y, 0.f) * v2.y
                  + fmaxf(z.z, 0.f) * v2.z + fmaxf(z.w, 0.f) * v2.w;
    #pragma unroll
    for (int off = 16; off; off >>= 1)
        partial += __shfl_xor_sync(0xffffffffu, partial, off);
    if (lane == 0) {
        float v = partial + bm2[0];
        out[e] = 1.f / (1.f + expf(-v));
    }
}

// ---------- launcher ----------
extern "C" void kernel_launch(void* const* d_in, const int* in_sizes, int n_in,
                              void* d_out, int out_size) {
    const float* x    = (const float*)d_in[0];
    const float* ea   = (const float*)d_in[1];
    const float* W1   = (const float*)d_in[2];
    const float* b1   = (const float*)d_in[3];
    const float* W2   = (const float*)d_in[4];
    const float* b2   = (const float*)d_in[5];
    const float* Wm1  = (const float*)d_in[6];
    const float* bm1  = (const float*)d_in[7];
    const float* Wm2  = (const float*)d_in[8];
    const float* bm2  = (const float*)d_in[9];
    const int*   ei   = (const int*)d_in[10];   // int32 (JAX x64 disabled)
    float* out = (float*)d_out;

    int n = in_sizes[0] / 5;          // 50000
    int E = in_sizes[10] / 2;         // 800000
    int nb = (n + 255) / 256;

    void *p_deg, *p_cur;
    float *p_t, *p_ab, *p_w2ab, *p_bab;
    cudaGetSymbolAddress(&p_deg, g_deg);
    cudaGetSymbolAddress(&p_cur, g_cur);
    cudaGetSymbolAddress((void**)&p_t, g_t);
    cudaGetSymbolAddress((void**)&p_ab, g_ab);
    cudaGetSymbolAddress((void**)&p_w2ab, g_w2ab);
    cudaGetSymbolAddress((void**)&p_bab, g_bab);

    // graph build
    cudaMemsetAsync(p_deg, 0, (size_t)n * sizeof(int), 0);
    cudaMemsetAsync(p_cur, 0, (size_t)n * sizeof(int), 0);
    indeg_kernel<<<(E + 255) / 256, 256>>>(ei, E);
    dis_kernel<<<(n + 255) / 256, 256>>>(n);
    bsum_kernel<<<nb, 256>>>(n);
    bscan_kernel<<<1, 256>>>(nb, n);
    rowptr_kernel<<<nb, 256>>>(n);
    fill_kernel<<<(E + 255) / 256, 256>>>(ei, E);

    // combined weights (tiny, overlaps with build tail on same stream order)
    wcomb_kernel<<<128, 256>>>(W2, Wm1);
    wbias_kernel<<<1, 256>>>(b2, Wm1);

    // layer 1: u1 = agg(x) (5-dim!) ; h1 = relu(u1@W1 + b1)
    aggx_kernel<<<(n * 32 + 255) / 256, 256>>>(x, n);
    gemm1_kernel<<<(n + 7) / 8, 128>>>(W1, b1, n);

    // layer 2 folded into projections: u2 = agg(h1) ; [A|B] = u2 @ W2AB + bAB
    agg2_kernel<<<(n * 32 + 255) / 256, 256>>>(n);
    gemm128_kernel<<<(n + 63) / 64, 256>>>(p_t, p_w2ab,       256, p_bab,       p_ab,       256, n);
    gemm128_kernel<<<(n + 63) / 64, 256>>>(p_t, p_w2ab + 128, 256, p_bab + 128, p_ab + 128, 256, n);

    // per-edge head
    edge_kernel<<<(E + 7) / 8, 256>>>(ei, ea, Wm1 + 256 * HID, bm1, Wm2, bm2, out, E);
}

// round 7
// speedup vs baseline: 1.4174x; 1.1867x over previous
#include <cuda_runtime.h>
#include <math.h>

#define NN 50000
#define NE 800000
#define HID 128

// ---------- static scratch (allocation-free contract) ----------
struct __align__(8) CsrEnt { int c; float w; };
__device__ int    g_deg[NN];
__device__ int    g_cur[NN];
__device__ float  g_dis[NN];
__device__ int    g_rowptr[NN + 1];
__device__ CsrEnt g_csr[NE];
__device__ int2   g_se[NE];                 // (src, edge_id) per CSR slot
__device__ int    g_bsum[256];
__device__ int    g_boff[256];
__device__ float  g_t[(size_t)NN * HID];    // u2 [n,128]
__device__ float  g_h[(size_t)NN * HID];    // h1 [n,128]
__device__ float  g_ab[(size_t)NN * 256];   // [A | B] per node
__device__ float  g_w2ab[128 * 256];        // W2 @ [W_A | W_B]
__device__ float  g_bab[256];               // b2 @ [W_A | W_B]

// ---------- f32x2 packed FMA (PTX-only; exact fp32 semantics) ----------
__device__ __forceinline__ unsigned long long ffma2(unsigned long long a,
                                                    unsigned long long b,
                                                    unsigned long long c) {
    unsigned long long d;
    asm("fma.rn.f32x2 %0, %1, %2, %3;" : "=l"(d) : "l"(a), "l"(b), "l"(c));
    return d;
}

// ---------- graph build ----------
__global__ void zero_kernel(int n) {
    int i = blockIdx.x * blockDim.x + threadIdx.x;
    if (i < n) { g_deg[i] = 0; g_cur[i] = 0; }
}

__global__ void indeg_kernel(const int* __restrict__ ei, int E) {
    int e = blockIdx.x * blockDim.x + threadIdx.x;
    if (e < E) atomicAdd(&g_deg[ei[E + e]], 1);
}

// dis + per-block degree sums (fused)
__global__ void disbsum_kernel(int n) {
    __shared__ int sm[8];
    int b = blockIdx.x;
    int i = b * 256 + threadIdx.x;
    int v = (i < n) ? g_deg[i] : 0;
    if (i < n) g_dis[i] = rsqrtf((float)(v + 1));
    int lane = threadIdx.x & 31, wid = threadIdx.x >> 5;
    int s = v;
    #pragma unroll
    for (int off = 16; off; off >>= 1) s += __shfl_xor_sync(0xffffffffu, s, off);
    if (lane == 0) sm[wid] = s;
    __syncthreads();
    if (wid == 0) {
        int t = (lane < 8) ? sm[lane] : 0;
        #pragma unroll
        for (int off = 4; off; off >>= 1) t += __shfl_xor_sync(0xffffffffu, t, off);
        if (lane == 0) g_bsum[b] = t;
    }
}

__global__ void bscan_kernel(int nb, int n) {
    __shared__ int wsum[8];
    int tid = threadIdx.x, lane = tid & 31, wid = tid >> 5;
    int v = (tid < nb) ? g_bsum[tid] : 0;
    int s = v;
    #pragma unroll
    for (int off = 1; off < 32; off <<= 1) {
        int t = __shfl_up_sync(0xffffffffu, s, off);
        if (lane >= off) s += t;
    }
    if (lane == 31) wsum[wid] = s;
    __syncthreads();
    if (wid == 0 && lane < 8) {
        int ws = wsum[lane];
        #pragma unroll
        for (int off = 1; off < 8; off <<= 1) {
            int t = __shfl_up_sync(0xffu, ws, off);
            if (lane >= off) ws += t;
        }
        wsum[lane] = ws;
    }
    __syncthreads();
    int incl = s + ((wid > 0) ? wsum[wid - 1] : 0);
    if (tid < nb) g_boff[tid] = incl - v;
    if (tid == nb - 1) g_rowptr[n] = incl;
}

__global__ void rowptr_kernel(int n) {
    __shared__ int wsum[8];
    int b = blockIdx.x;
    int i = b * 256 + threadIdx.x;
    int tid = threadIdx.x, lane = tid & 31, wid = tid >> 5;
    int v = (i < n) ? g_deg[i] : 0;
    int s = v;
    #pragma unroll
    for (int off = 1; off < 32; off <<= 1) {
        int t = __shfl_up_sync(0xffffffffu, s, off);
        if (lane >= off) s += t;
    }
    if (lane == 31) wsum[wid] = s;
    __syncthreads();
    if (wid == 0 && lane < 8) {
        int ws = wsum[lane];
        #pragma unroll
        for (int off = 1; off < 8; off <<= 1) {
            int t = __shfl_up_sync(0xffu, ws, off);
            if (lane >= off) ws += t;
        }
        wsum[lane] = ws;
    }
    __syncthreads();
    int excl = s - v + ((wid > 0) ? wsum[wid - 1] : 0);
    if (i < n) g_rowptr[i] = g_boff[b] + excl;
}

__global__ void fill_kernel(const int* __restrict__ ei, int E) {
    int e = blockIdx.x * blockDim.x + threadIdx.x;
    if (e >= E) return;
    int s = ei[e];
    int c = ei[E + e];
    int pos = g_rowptr[c] + atomicAdd(&g_cur[c], 1);
    CsrEnt en; en.c = s; en.w = g_dis[s] * g_dis[c];
    g_csr[pos] = en;
    g_se[pos] = make_int2(s, e);
}

// ---------- combined weights: W2AB = W2 @ [W_A | W_B] ----------
__global__ void wcomb_kernel(const float* __restrict__ W2, const float* __restrict__ Wm1) {
    __shared__ float w2row[128];
    int k = blockIdx.x;       // output row
    int j = threadIdx.x;      // output col 0..255
    if (j < 128) w2row[j] = W2[k * 128 + j];
    __syncthreads();
    const float* base = (j < 128) ? (Wm1 + j) : (Wm1 + 128 * 128 + (j - 128));
    float acc = 0.f;
    #pragma unroll 8
    for (int q = 0; q < 128; q++) acc += w2row[q] * base[(size_t)q * 128];
    g_w2ab[k * 256 + j] = acc;
}

__global__ void wbias_kernel(const float* __restrict__ b2, const float* __restrict__ Wm1) {
    int j = threadIdx.x;
    const float* base = (j < 128) ? (Wm1 + j) : (Wm1 + 128 * 128 + (j - 128));
    float acc = 0.f;
    #pragma unroll 8
    for (int k = 0; k < 128; k++) acc += b2[k] * base[(size_t)k * 128];
    g_bab[j] = acc;
}

// ---------- fused layer 1: u1 = agg(x) (5-dim), h1 = relu(u1@W1 + b1) ----------
__global__ void aggx_gemm1_kernel(const float* __restrict__ x, const float* __restrict__ W1,
                                  const float* __restrict__ b1, int n) {
    __shared__ float Ws[5][HID];
    __shared__ float bs[HID];
    int tid = threadIdx.x;   // 256
    if (tid < HID) {
        #pragma unroll
        for (int f = 0; f < 5; f++) Ws[f][tid] = W1[f * HID + tid];
        bs[tid] = b1[tid];
    }
    __syncthreads();
    int gwid = (blockIdx.x * blockDim.x + tid) >> 5;
    int lane = tid & 31;
    if (gwid >= n) return;
    int node = gwid;
    int beg = g_rowptr[node], end = g_rowptr[node + 1];
    float s0 = 0.f, s1 = 0.f, s2 = 0.f, s3 = 0.f, s4 = 0.f;
    for (int e = beg + lane; e < end; e += 32) {
        unsigned long long raw = __ldg((const unsigned long long*)&g_csr[e]);
        CsrEnt en = *(CsrEnt*)&raw;
        const float* xr = x + (size_t)en.c * 5;
        s0 += en.w * xr[0]; s1 += en.w * xr[1]; s2 += en.w * xr[2];
        s3 += en.w * xr[3]; s4 += en.w * xr[4];
    }
    #pragma unroll
    for (int off = 16; off; off >>= 1) {
        s0 += __shfl_xor_sync(0xffffffffu, s0, off);
        s1 += __shfl_xor_sync(0xffffffffu, s1, off);
        s2 += __shfl_xor_sync(0xffffffffu, s2, off);
        s3 += __shfl_xor_sync(0xffffffffu, s3, off);
        s4 += __shfl_xor_sync(0xffffffffu, s4, off);
    }
    float d = g_dis[node];
    float self = d * d;
    const float* xn = x + (size_t)node * 5;
    float u0 = s0 + self * xn[0];
    float u1 = s1 + self * xn[1];
    float u2 = s2 + self * xn[2];
    float u3 = s3 + self * xn[3];
    float u4 = s4 + self * xn[4];
    float4 h;
    int c = lane * 4;
    h.x = fmaxf(bs[c+0] + u0*Ws[0][c+0] + u1*Ws[1][c+0] + u2*Ws[2][c+0] + u3*Ws[3][c+0] + u4*Ws[4][c+0], 0.f);
    h.y = fmaxf(bs[c+1] + u0*Ws[0][c+1] + u1*Ws[1][c+1] + u2*Ws[2][c+1] + u3*Ws[3][c+1] + u4*Ws[4][c+1], 0.f);
    h.z = fmaxf(bs[c+2] + u0*Ws[0][c+2] + u1*Ws[1][c+2] + u2*Ws[2][c+2] + u3*Ws[3][c+2] + u4*Ws[4][c+2], 0.f);
    h.w = fmaxf(bs[c+3] + u0*Ws[0][c+3] + u1*Ws[1][c+3] + u2*Ws[2][c+3] + u3*Ws[3][c+3] + u4*Ws[4][c+3], 0.f);
    *((float4*)(g_h + (size_t)node * HID) + lane) = h;
}

// ---------- layer-2 aggregation: u2 = agg(h1), float4 rows ----------
__global__ void agg2_kernel(int n) {
    int gwid = (blockIdx.x * blockDim.x + threadIdx.x) >> 5;
    int lane = threadIdx.x & 31;
    if (gwid >= n) return;
    int node = gwid;
    float d = g_dis[node];
    float self = d * d;
    float4 hv = *((const float4*)(g_h + (size_t)node * HID) + lane);
    float4 acc = make_float4(self * hv.x, self * hv.y, self * hv.z, self * hv.w);
    int beg = g_rowptr[node], end = g_rowptr[node + 1];
    int e = beg;
    for (; e + 1 < end; e += 2) {
        unsigned long long r0 = __ldg((const unsigned long long*)&g_csr[e]);
        unsigned long long r1 = __ldg((const unsigned long long*)&g_csr[e + 1]);
        CsrEnt e0 = *(CsrEnt*)&r0;
        CsrEnt e1 = *(CsrEnt*)&r1;
        float4 v0 = __ldg((const float4*)(g_h + (size_t)e0.c * HID) + lane);
        float4 v1 = __ldg((const float4*)(g_h + (size_t)e1.c * HID) + lane);
        acc.x += e0.w * v0.x; acc.y += e0.w * v0.y; acc.z += e0.w * v0.z; acc.w += e0.w * v0.w;
        acc.x += e1.w * v1.x; acc.y += e1.w * v1.y; acc.z += e1.w * v1.z; acc.w += e1.w * v1.w;
    }
    if (e < end) {
        unsigned long long r0 = __ldg((const unsigned long long*)&g_csr[e]);
        CsrEnt e0 = *(CsrEnt*)&r0;
        float4 v0 = __ldg((const float4*)(g_h + (size_t)e0.c * HID) + lane);
        acc.x += e0.w * v0.x; acc.y += e0.w * v0.y; acc.z += e0.w * v0.z; acc.w += e0.w * v0.w;
    }
    *((float4*)(g_t + (size_t)node * HID) + lane) = acc;
}

// ---------- [A|B] = u2 @ W2AB + bAB : [n,128] @ [128,256] (packed f32x2) ----------
// 256 threads, tile 64 rows x 256 cols, thread = 8 rows x 8 cols. K-chunk 16.
__global__ void gemm256_kernel(const float* __restrict__ H, const float* __restrict__ W,
                               const float* __restrict__ bias, float* __restrict__ O, int n) {
    __shared__ float4 Wsa[16][32];   // cols c8*8..+3
    __shared__ float4 Wsb[16][32];   // cols c8*8+4..+7
    __shared__ float2 Hs2[16][66];   // duplicated (h,h) per row
    int tid = threadIdx.x;
    int c8  = tid & 31;
    int r0  = (tid >> 5) * 8;
    int row0 = blockIdx.x * 64;

    unsigned long long acc[8][4];
    #pragma unroll
    for (int r = 0; r < 8; r++)
        #pragma unroll
        for (int j = 0; j < 4; j++) acc[r][j] = 0ull;

    for (int k0 = 0; k0 < HID; k0 += 16) {
        #pragma unroll
        for (int i = 0; i < 4; i++) {
            int q = tid + i * 256;          // 0..1023 float4 slots of W chunk
            int kk = q >> 6, cc = q & 63;
            float4 v = *(const float4*)&W[(size_t)(k0 + kk) * 256 + cc * 4];
            if (cc & 1) Wsb[kk][cc >> 1] = v; else Wsa[kk][cc >> 1] = v;
        }
        {
            int q = tid;                     // 0..255 float4 slots of H chunk
            int r = q >> 2, kq = (q & 3) * 4;
            int gr = row0 + r;
            float4 hv = make_float4(0.f, 0.f, 0.f, 0.f);
            if (gr < n) hv = *(const float4*)&H[(size_t)gr * HID + k0 + kq];
            Hs2[kq + 0][r] = make_float2(hv.x, hv.x);
            Hs2[kq + 1][r] = make_float2(hv.y, hv.y);
            Hs2[kq + 2][r] = make_float2(hv.z, hv.z);
            Hs2[kq + 3][r] = make_float2(hv.w, hv.w);
        }
        __syncthreads();
        #pragma unroll
        for (int kk = 0; kk < 16; kk++) {
            ulonglong2 wa = *(ulonglong2*)&Wsa[kk][c8];
            ulonglong2 wb = *(ulonglong2*)&Wsb[kk][c8];
            #pragma unroll
            for (int r = 0; r < 8; r++) {
                unsigned long long h2 = *(unsigned long long*)&Hs2[kk][r0 + r];
                acc[r][0] = ffma2(h2, wa.x, acc[r][0]);
                acc[r][1] = ffma2(h2, wa.y, acc[r][1]);
                acc[r][2] = ffma2(h2, wb.x, acc[r][2]);
                acc[r][3] = ffma2(h2, wb.y, acc[r][3]);
            }
        }
        __syncthreads();
    }
    float4 bv0 = *(const float4*)&bias[c8 * 8];
    float4 bv1 = *(const float4*)&bias[c8 * 8 + 4];
    #pragma unroll
    for (int r = 0; r < 8; r++) {
        int gr = row0 + r0 + r;
        if (gr < n) {
            float2 p0 = *(float2*)&acc[r][0];
            float2 p1 = *(float2*)&acc[r][1];
            float2 p2 = *(float2*)&acc[r][2];
            float2 p3 = *(float2*)&acc[r][3];
            float4 o0 = make_float4(p0.x + bv0.x, p0.y + bv0.y, p1.x + bv0.z, p1.y + bv0.w);
            float4 o1 = make_float4(p2.x + bv1.x, p2.y + bv1.y, p3.x + bv1.z, p3.y + bv1.w);
            *(float4*)&O[(size_t)gr * 256 + c8 * 8]     = o0;
            *(float4*)&O[(size_t)gr * 256 + c8 * 8 + 4] = o1;
        }
    }
}

// ---------- per-edge MLP head, grouped by dst: one warp per node ----------
// B[dst] held in registers across the node's edges; gathers only A[src] + ea.
__global__ void edge_kernel(const float* __restrict__ ea,
                            const float* __restrict__ WmE,
                            const float* __restrict__ bm1, const float* __restrict__ Wm2,
                            const float* __restrict__ bm2, float* __restrict__ out, int n) {
    __shared__ float4 sWe[4][32];
    __shared__ float4 sb4[32];
    __shared__ float4 sw24[32];
    __shared__ float sbm2;
    int tid = threadIdx.x;  // 256
    if (tid < 128) sWe[tid >> 5][tid & 31] = *(const float4*)&WmE[(tid >> 5) * HID + (tid & 31) * 4];
    else if (tid < 160) sb4[tid - 128] = *(const float4*)&bm1[(tid - 128) * 4];
    else if (tid < 192) sw24[tid - 160] = *(const float4*)&Wm2[(tid - 160) * 4];
    else if (tid == 192) sbm2 = bm2[0];
    __syncthreads();
    int gwid = (blockIdx.x * blockDim.x + tid) >> 5;
    int lane = tid & 31;
    if (gwid >= n) return;
    int node = gwid;
    int beg = g_rowptr[node], end = g_rowptr[node + 1];
    if (beg == end) return;
    float4 Bb = *(const float4*)&g_ab[(size_t)node * 256 + HID + lane * 4];
    float4 bi = sb4[lane];
    Bb.x += bi.x; Bb.y += bi.y; Bb.z += bi.z; Bb.w += bi.w;
    float4 w0 = sWe[0][lane], w1 = sWe[1][lane], w2 = sWe[2][lane], w3 = sWe[3][lane];
    float4 v2 = sw24[lane];
    float bm2v = sbm2;
    int e = beg;
    for (; e + 1 < end; e += 2) {
        int2 se0 = __ldg(&g_se[e]);
        int2 se1 = __ldg(&g_se[e + 1]);
        float4 A0 = __ldg((const float4*)(g_ab + (size_t)se0.x * 256) + lane);
        float4 A1 = __ldg((const float4*)(g_ab + (size_t)se1.x * 256) + lane);
        float4 ev0 = __ldg((const float4*)&ea[(size_t)se0.y * 4]);
        float4 ev1 = __ldg((const float4*)&ea[(size_t)se1.y * 4]);
        float4 z0, z1;
        z0.x = A0.x + Bb.x + ev0.x*w0.x + ev0.y*w1.x + ev0.z*w2.x + ev0.w*w3.x;
        z0.y = A0.y + Bb.y + ev0.x*w0.y + ev0.y*w1.y + ev0.z*w2.y + ev0.w*w3.y;
        z0.z = A0.z + Bb.z + ev0.x*w0.z + ev0.y*w1.z + ev0.z*w2.z + ev0.w*w3.z;
        z0.w = A0.w + Bb.w + ev0.x*w0.w + ev0.y*w1.w + ev0.z*w2.w + ev0.w*w3.w;
        z1.x = A1.x + Bb.x + ev1.x*w0.x + ev1.y*w1.x + ev1.z*w2.x + ev1.w*w3.x;
        z1.y = A1.y + Bb.y + ev1.x*w0.y + ev1.y*w1.y + ev1.z*w2.y + ev1.w*w3.y;
        z1.z = A1.z + Bb.z + ev1.x*w0.z + ev1.y*w1.z + ev1.z*w2.z + ev1.w*w3.z;
        z1.w = A1.w + Bb.w + ev1.x*w0.w + ev1.y*w1.w + ev1.z*w2.w + ev1.w*w3.w;
        float p0 = fmaxf(z0.x,0.f)*v2.x + fmaxf(z0.y,0.f)*v2.y + fmaxf(z0.z,0.f)*v2.z + fmaxf(z0.w,0.f)*v2.w;
        float p1 = fmaxf(z1.x,0.f)*v2.x + fmaxf(z1.y,0.f)*v2.y + fmaxf(z1.z,0.f)*v2.z + fmaxf(z1.w,0.f)*v2.w;
        #pragma unroll
        for (int off = 16; off; off >>= 1) {
            p0 += __shfl_xor_sync(0xffffffffu, p0, off);
            p1 += __shfl_xor_sync(0xffffffffu, p1, off);
        }
        if (lane == 0) out[se0.y] = 1.f / (1.f + __expf(-(p0 + bm2v)));
        if (lane == 1) out[se1.y] = 1.f / (1.f + __expf(-(p1 + bm2v)));
    }
    if (e < end) {
        int2 se0 = __ldg(&g_se[e]);
        float4 A0 = __ldg((const float4*)(g_ab + (size_t)se0.x * 256) + lane);
        float4 ev0 = __ldg((const float4*)&ea[(size_t)se0.y * 4]);
        float4 z0;
        z0.x = A0.x + Bb.x + ev0.x*w0.x + ev0.y*w1.x + ev0.z*w2.x + ev0.w*w3.x;
        z0.y = A0.y + Bb.y + ev0.x*w0.y + ev0.y*w1.y + ev0.z*w2.y + ev0.w*w3.y;
        z0.z = A0.z + Bb.z + ev0.x*w0.z + ev0.y*w1.z + ev0.z*w2.z + ev0.w*w3.z;
        z0.w = A0.w + Bb.w + ev0.x*w0.w + ev0.y*w1.w + ev0.z*w2.w + ev0.w*w3.w;
        float p0 = fmaxf(z0.x,0.f)*v2.x + fmaxf(z0.y,0.f)*v2.y + fmaxf(z0.z,0.f)*v2.z + fmaxf(z0.w,0.f)*v2.w;
        #pragma unroll
        for (int off = 16; off; off >>= 1)
            p0 += __shfl_xor_sync(0xffffffffu, p0, off);
        if (lane == 0) out[se0.y] = 1.f / (1.f + __expf(-(p0 + bm2v)));
    }
}

// ---------- launcher ----------
extern "C" void kernel_launch(void* const* d_in, const int* in_sizes, int n_in,
                              void* d_out, int out_size) {
    const float* x    = (const float*)d_in[0];
    const float* ea   = (const float*)d_in[1];
    const float* W1   = (const float*)d_in[2];
    const float* b1   = (const float*)d_in[3];
    const float* W2   = (const float*)d_in[4];
    const float* b2   = (const float*)d_in[5];
    const float* Wm1  = (const float*)d_in[6];
    const float* bm1  = (const float*)d_in[7];
    const float* Wm2  = (const float*)d_in[8];
    const float* bm2  = (const float*)d_in[9];
    const int*   ei   = (const int*)d_in[10];   // int32 (JAX x64 disabled)
    float* out = (float*)d_out;

    int n = in_sizes[0] / 5;          // 50000
    int E = in_sizes[10] / 2;         // 800000
    int nb = (n + 255) / 256;

    float *p_t, *p_ab, *p_w2ab, *p_bab;
    cudaGetSymbolAddress((void**)&p_t, g_t);
    cudaGetSymbolAddress((void**)&p_ab, g_ab);
    cudaGetSymbolAddress((void**)&p_w2ab, g_w2ab);
    cudaGetSymbolAddress((void**)&p_bab, g_bab);

    // graph build (launch #5 = fill_kernel -> gets profiled)
    zero_kernel<<<nb, 256>>>(n);
    indeg_kernel<<<(E + 255) / 256, 256>>>(ei, E);
    disbsum_kernel<<<nb, 256>>>(n);
    bscan_kernel<<<1, 256>>>(nb, n);
    rowptr_kernel<<<nb, 256>>>(n);
    fill_kernel<<<(E + 255) / 256, 256>>>(ei, E);

    // combined weights
    wcomb_kernel<<<128, 256>>>(W2, Wm1);
    wbias_kernel<<<1, 256>>>(b2, Wm1);

    // layer 1 fused: h1 = relu(agg(x) @ W1 + b1)
    aggx_gemm1_kernel<<<(n * 32 + 255) / 256, 256>>>(x, W1, b1, n);

    // layer 2 folded: u2 = agg(h1) ; [A|B] = u2 @ W2AB + bAB  (one pass)
    agg2_kernel<<<(n * 32 + 255) / 256, 256>>>(n);
    gemm256_kernel<<<(n + 63) / 64, 256>>>(p_t, p_w2ab, p_bab, p_ab, n);

    // per-edge head grouped by dst
    edge_kernel<<<(n * 32 + 255) / 256, 256>>>(ea, Wm1 + 256 * HID, bm1, Wm2, bm2, out, n);
}

// round 8
// speedup vs baseline: 1.4266x; 1.0065x over previous
#include <cuda_runtime.h>
#include <math.h>

#define NN 50000
#define NE 800000
#define HID 128

// ---------- static scratch (allocation-free contract) ----------
struct __align__(8) CsrEnt { int c; float w; };
__device__ int    g_deg[NN];
__device__ int    g_cur[NN];
__device__ float  g_dis[NN];
__device__ int    g_rowptr[NN + 1];
__device__ CsrEnt g_csr[NE];
__device__ int2   g_se[NE];                 // (src, edge_id) per CSR slot
__device__ int    g_bsum[256];
__device__ float  g_t[(size_t)NN * HID];    // u2 [n,128]
__device__ float  g_h[(size_t)NN * HID];    // h1 [n,128]
__device__ float  g_ab[(size_t)NN * 256];   // [A | B] per node
__device__ float  g_w2ab[128 * 256];        // W2 @ [W_A | W_B]
__device__ float  g_bab[256];               // b2 @ [W_A | W_B]

// ---------- f32x2 packed FMA (PTX-only; exact fp32 semantics) ----------
__device__ __forceinline__ unsigned long long ffma2(unsigned long long a,
                                                    unsigned long long b,
                                                    unsigned long long c) {
    unsigned long long d;
    asm("fma.rn.f32x2 %0, %1, %2, %3;" : "=l"(d) : "l"(a), "l"(b), "l"(c));
    return d;
}

// ---------- graph build ----------
__global__ void indeg_kernel(const int* __restrict__ ei, int E) {
    int e = blockIdx.x * blockDim.x + threadIdx.x;
    if (e < E) atomicAdd(&g_deg[ei[E + e]], 1);
}

// dis + per-block degree sums (fused)
__global__ void disbsum_kernel(int n) {
    __shared__ int sm[8];
    int b = blockIdx.x;
    int i = b * 256 + threadIdx.x;
    int v = (i < n) ? g_deg[i] : 0;
    if (i < n) g_dis[i] = rsqrtf((float)(v + 1));
    int lane = threadIdx.x & 31, wid = threadIdx.x >> 5;
    int s = v;
    #pragma unroll
    for (int off = 16; off; off >>= 1) s += __shfl_xor_sync(0xffffffffu, s, off);
    if (lane == 0) sm[wid] = s;
    __syncthreads();
    if (wid == 0) {
        int t = (lane < 8) ? sm[lane] : 0;
        #pragma unroll
        for (int off = 4; off; off >>= 1) t += __shfl_xor_sync(0xffffffffu, t, off);
        if (lane == 0) g_bsum[b] = t;
    }
}

// rowptr in one kernel: every block reduces block-sums itself (nb<=256), then local scan
__global__ void rowptr2_kernel(int nb, int n) {
    __shared__ unsigned long long psm[8];
    __shared__ int wsum[8];
    __shared__ int s_boff, s_tot;
    int b = blockIdx.x, tid = threadIdx.x;
    int lane = tid & 31, wid = tid >> 5;

    // packed reduce: lo = sum_{i<b} bsum[i] (block offset), hi = total
    unsigned long long pv = 0ull;
    if (tid < nb) {
        unsigned long long xv = (unsigned int)g_bsum[tid];
        pv = (xv << 32) | ((tid < b) ? xv : 0ull);
    }
    #pragma unroll
    for (int off = 16; off; off >>= 1) pv += __shfl_xor_sync(0xffffffffu, pv, off);
    if (lane == 0) psm[wid] = pv;
    __syncthreads();
    if (wid == 0) {
        unsigned long long t = (lane < 8) ? psm[lane] : 0ull;
        #pragma unroll
        for (int off = 4; off; off >>= 1) t += __shfl_xor_sync(0xffffffffu, t, off);
        if (lane == 0) { s_boff = (int)(t & 0xffffffffull); s_tot = (int)(t >> 32); }
    }
    __syncthreads();

    // local exclusive scan of degrees within this block
    int i = b * 256 + tid;
    int v = (i < n) ? g_deg[i] : 0;
    int s = v;
    #pragma unroll
    for (int off = 1; off < 32; off <<= 1) {
        int t = __shfl_up_sync(0xffffffffu, s, off);
        if (lane >= off) s += t;
    }
    if (lane == 31) wsum[wid] = s;
    __syncthreads();
    if (wid == 0 && lane < 8) {
        int ws = wsum[lane];
        #pragma unroll
        for (int off = 1; off < 8; off <<= 1) {
            int t = __shfl_up_sync(0xffu, ws, off);
            if (lane >= off) ws += t;
        }
        wsum[lane] = ws;
    }
    __syncthreads();
    int excl = s - v + ((wid > 0) ? wsum[wid - 1] : 0);
    if (i < n) g_rowptr[i] = s_boff + excl;
    if (b == gridDim.x - 1 && tid == 0) g_rowptr[n] = s_tot;
}

__global__ void fill_kernel(const int* __restrict__ ei, int E) {
    int e = blockIdx.x * blockDim.x + threadIdx.x;
    if (e >= E) return;
    int s = ei[e];
    int c = ei[E + e];
    int pos = g_rowptr[c] + atomicAdd(&g_cur[c], 1);
    CsrEnt en; en.c = s; en.w = g_dis[s] * g_dis[c];
    g_csr[pos] = en;
    g_se[pos] = make_int2(s, e);
}

// ---------- combined weights: W2AB = W2 @ [W_A | W_B] ----------
__global__ void wcomb_kernel(const float* __restrict__ W2, const float* __restrict__ Wm1) {
    __shared__ float w2row[128];
    int k = blockIdx.x;
    int j = threadIdx.x;
    if (j < 128) w2row[j] = W2[k * 128 + j];
    __syncthreads();
    const float* base = (j < 128) ? (Wm1 + j) : (Wm1 + 128 * 128 + (j - 128));
    float acc = 0.f;
    #pragma unroll 8
    for (int q = 0; q < 128; q++) acc += w2row[q] * base[(size_t)q * 128];
    g_w2ab[k * 256 + j] = acc;
}

__global__ void wbias_kernel(const float* __restrict__ b2, const float* __restrict__ Wm1) {
    int j = threadIdx.x;
    const float* base = (j < 128) ? (Wm1 + j) : (Wm1 + 128 * 128 + (j - 128));
    float acc = 0.f;
    #pragma unroll 8
    for (int k = 0; k < 128; k++) acc += b2[k] * base[(size_t)k * 128];
    g_bab[j] = acc;
}

// ---------- fused layer 1: u1 = agg(x) (5-dim), h1 = relu(u1@W1 + b1) ----------
__global__ void aggx_gemm1_kernel(const float* __restrict__ x, const float* __restrict__ W1,
                                  const float* __restrict__ b1, int n) {
    __shared__ float Ws[5][HID];
    __shared__ float bs[HID];
    int tid = threadIdx.x;   // 256
    if (tid < HID) {
        #pragma unroll
        for (int f = 0; f < 5; f++) Ws[f][tid] = W1[f * HID + tid];
        bs[tid] = b1[tid];
    }
    __syncthreads();
    int gwid = (blockIdx.x * blockDim.x + tid) >> 5;
    int lane = tid & 31;
    if (gwid >= n) return;
    int node = gwid;
    int beg = g_rowptr[node], end = g_rowptr[node + 1];
    float s0 = 0.f, s1 = 0.f, s2 = 0.f, s3 = 0.f, s4 = 0.f;
    for (int e = beg + lane; e < end; e += 32) {
        unsigned long long raw = __ldg((const unsigned long long*)&g_csr[e]);
        CsrEnt en = *(CsrEnt*)&raw;
        const float* xr = x + (size_t)en.c * 5;
        s0 += en.w * xr[0]; s1 += en.w * xr[1]; s2 += en.w * xr[2];
        s3 += en.w * xr[3]; s4 += en.w * xr[4];
    }
    #pragma unroll
    for (int off = 16; off; off >>= 1) {
        s0 += __shfl_xor_sync(0xffffffffu, s0, off);
        s1 += __shfl_xor_sync(0xffffffffu, s1, off);
        s2 += __shfl_xor_sync(0xffffffffu, s2, off);
        s3 += __shfl_xor_sync(0xffffffffu, s3, off);
        s4 += __shfl_xor_sync(0xffffffffu, s4, off);
    }
    float d = g_dis[node];
    float self = d * d;
    const float* xn = x + (size_t)node * 5;
    float u0 = s0 + self * xn[0];
    float u1 = s1 + self * xn[1];
    float u2 = s2 + self * xn[2];
    float u3 = s3 + self * xn[3];
    float u4 = s4 + self * xn[4];
    float4 h;
    int c = lane * 4;
    h.x = fmaxf(bs[c+0] + u0*Ws[0][c+0] + u1*Ws[1][c+0] + u2*Ws[2][c+0] + u3*Ws[3][c+0] + u4*Ws[4][c+0], 0.f);
    h.y = fmaxf(bs[c+1] + u0*Ws[0][c+1] + u1*Ws[1][c+1] + u2*Ws[2][c+1] + u3*Ws[3][c+1] + u4*Ws[4][c+1], 0.f);
    h.z = fmaxf(bs[c+2] + u0*Ws[0][c+2] + u1*Ws[1][c+2] + u2*Ws[2][c+2] + u3*Ws[3][c+2] + u4*Ws[4][c+2], 0.f);
    h.w = fmaxf(bs[c+3] + u0*Ws[0][c+3] + u1*Ws[1][c+3] + u2*Ws[2][c+3] + u3*Ws[3][c+3] + u4*Ws[4][c+3], 0.f);
    *((float4*)(g_h + (size_t)node * HID) + lane) = h;
}

// ---------- layer-2 aggregation: u2 = agg(h1), unroll 4 for MLP ----------
__global__ void agg2_kernel(int n) {
    int gwid = (blockIdx.x * blockDim.x + threadIdx.x) >> 5;
    int lane = threadIdx.x & 31;
    if (gwid >= n) return;
    int node = gwid;
    float d = g_dis[node];
    float self = d * d;
    float4 hv = *((const float4*)(g_h + (size_t)node * HID) + lane);
    float4 acc = make_float4(self * hv.x, self * hv.y, self * hv.z, self * hv.w);
    int beg = g_rowptr[node], end = g_rowptr[node + 1];
    int e = beg;
    for (; e + 3 < end; e += 4) {
        unsigned long long r0 = __ldg((const unsigned long long*)&g_csr[e]);
        unsigned long long r1 = __ldg((const unsigned long long*)&g_csr[e + 1]);
        unsigned long long r2 = __ldg((const unsigned long long*)&g_csr[e + 2]);
        unsigned long long r3 = __ldg((const unsigned long long*)&g_csr[e + 3]);
        CsrEnt e0 = *(CsrEnt*)&r0;
        CsrEnt e1 = *(CsrEnt*)&r1;
        CsrEnt e2 = *(CsrEnt*)&r2;
        CsrEnt e3 = *(CsrEnt*)&r3;
        float4 v0 = __ldg((const float4*)(g_h + (size_t)e0.c * HID) + lane);
        float4 v1 = __ldg((const float4*)(g_h + (size_t)e1.c * HID) + lane);
        float4 v2 = __ldg((const float4*)(g_h + (size_t)e2.c * HID) + lane);
        float4 v3 = __ldg((const float4*)(g_h + (size_t)e3.c * HID) + lane);
        acc.x += e0.w * v0.x; acc.y += e0.w * v0.y; acc.z += e0.w * v0.z; acc.w += e0.w * v0.w;
        acc.x += e1.w * v1.x; acc.y += e1.w * v1.y; acc.z += e1.w * v1.z; acc.w += e1.w * v1.w;
        acc.x += e2.w * v2.x; acc.y += e2.w * v2.y; acc.z += e2.w * v2.z; acc.w += e2.w * v2.w;
        acc.x += e3.w * v3.x; acc.y += e3.w * v3.y; acc.z += e3.w * v3.z; acc.w += e3.w * v3.w;
    }
    for (; e < end; e++) {
        unsigned long long r0 = __ldg((const unsigned long long*)&g_csr[e]);
        CsrEnt e0 = *(CsrEnt*)&r0;
        float4 v0 = __ldg((const float4*)(g_h + (size_t)e0.c * HID) + lane);
        acc.x += e0.w * v0.x; acc.y += e0.w * v0.y; acc.z += e0.w * v0.z; acc.w += e0.w * v0.w;
    }
    *((float4*)(g_t + (size_t)node * HID) + lane) = acc;
}

// ---------- [A|B] = u2 @ W2AB + bAB : [n,128] @ [128,256] (packed f32x2) ----------
__global__ void gemm256_kernel(const float* __restrict__ H, const float* __restrict__ W,
                               const float* __restrict__ bias, float* __restrict__ O, int n) {
    __shared__ float4 Wsa[16][32];
    __shared__ float4 Wsb[16][32];
    __shared__ float2 Hs2[16][66];
    int tid = threadIdx.x;
    int c8  = tid & 31;
    int r0  = (tid >> 5) * 8;
    int row0 = blockIdx.x * 64;

    unsigned long long acc[8][4];
    #pragma unroll
    for (int r = 0; r < 8; r++)
        #pragma unroll
        for (int j = 0; j < 4; j++) acc[r][j] = 0ull;

    for (int k0 = 0; k0 < HID; k0 += 16) {
        #pragma unroll
        for (int i = 0; i < 4; i++) {
            int q = tid + i * 256;
            int kk = q >> 6, cc = q & 63;
            float4 v = *(const float4*)&W[(size_t)(k0 + kk) * 256 + cc * 4];
            if (cc & 1) Wsb[kk][cc >> 1] = v; else Wsa[kk][cc >> 1] = v;
        }
        {
            int q = tid;
            int r = q >> 2, kq = (q & 3) * 4;
            int gr = row0 + r;
            float4 hv = make_float4(0.f, 0.f, 0.f, 0.f);
            if (gr < n) hv = *(const float4*)&H[(size_t)gr * HID + k0 + kq];
            Hs2[kq + 0][r] = make_float2(hv.x, hv.x);
            Hs2[kq + 1][r] = make_float2(hv.y, hv.y);
            Hs2[kq + 2][r] = make_float2(hv.z, hv.z);
            Hs2[kq + 3][r] = make_float2(hv.w, hv.w);
        }
        __syncthreads();
        #pragma unroll
        for (int kk = 0; kk < 16; kk++) {
            ulonglong2 wa = *(ulonglong2*)&Wsa[kk][c8];
            ulonglong2 wb = *(ulonglong2*)&Wsb[kk][c8];
            #pragma unroll
            for (int r = 0; r < 8; r++) {
                unsigned long long h2 = *(unsigned long long*)&Hs2[kk][r0 + r];
                acc[r][0] = ffma2(h2, wa.x, acc[r][0]);
                acc[r][1] = ffma2(h2, wa.y, acc[r][1]);
                acc[r][2] = ffma2(h2, wb.x, acc[r][2]);
                acc[r][3] = ffma2(h2, wb.y, acc[r][3]);
            }
        }
        __syncthreads();
    }
    float4 bv0 = *(const float4*)&bias[c8 * 8];
    float4 bv1 = *(const float4*)&bias[c8 * 8 + 4];
    #pragma unroll
    for (int r = 0; r < 8; r++) {
        int gr = row0 + r0 + r;
        if (gr < n) {
            float2 p0 = *(float2*)&acc[r][0];
            float2 p1 = *(float2*)&acc[r][1];
            float2 p2 = *(float2*)&acc[r][2];
            float2 p3 = *(float2*)&acc[r][3];
            float4 o0 = make_float4(p0.x + bv0.x, p0.y + bv0.y, p1.x + bv0.z, p1.y + bv0.w);
            float4 o1 = make_float4(p2.x + bv1.x, p2.y + bv1.y, p3.x + bv1.z, p3.y + bv1.w);
            *(float4*)&O[(size_t)gr * 256 + c8 * 8]     = o0;
            *(float4*)&O[(size_t)gr * 256 + c8 * 8 + 4] = o1;
        }
    }
}

// ---------- per-edge MLP head, grouped by dst, unroll 4 ----------
__device__ __forceinline__ float edge_dot(float4 A, float4 Bb, float4 ev,
                                          float4 w0, float4 w1, float4 w2, float4 w3,
                                          float4 v2) {
    float4 z;
    z.x = A.x + Bb.x + ev.x*w0.x + ev.y*w1.x + ev.z*w2.x + ev.w*w3.x;
    z.y = A.y + Bb.y + ev.x*w0.y + ev.y*w1.y + ev.z*w2.y + ev.w*w3.y;
    z.z = A.z + Bb.z + ev.x*w0.z + ev.y*w1.z + ev.z*w2.z + ev.w*w3.z;
    z.w = A.w + Bb.w + ev.x*w0.w + ev.y*w1.w + ev.z*w2.w + ev.w*w3.w;
    return fmaxf(z.x,0.f)*v2.x + fmaxf(z.y,0.f)*v2.y + fmaxf(z.z,0.f)*v2.z + fmaxf(z.w,0.f)*v2.w;
}

__global__ void edge_kernel(const float* __restrict__ ea,
                            const float* __restrict__ WmE,
                            const float* __restrict__ bm1, const float* __restrict__ Wm2,
                            const float* __restrict__ bm2, float* __restrict__ out, int n) {
    __shared__ float4 sWe[4][32];
    __shared__ float4 sb4[32];
    __shared__ float4 sw24[32];
    __shared__ float sbm2;
    int tid = threadIdx.x;  // 256
    if (tid < 128) sWe[tid >> 5][tid & 31] = *(const float4*)&WmE[(tid >> 5) * HID + (tid & 31) * 4];
    else if (tid < 160) sb4[tid - 128] = *(const float4*)&bm1[(tid - 128) * 4];
    else if (tid < 192) sw24[tid - 160] = *(const float4*)&Wm2[(tid - 160) * 4];
    else if (tid == 192) sbm2 = bm2[0];
    __syncthreads();
    int gwid = (blockIdx.x * blockDim.x + tid) >> 5;
    int lane = tid & 31;
    if (gwid >= n) return;
    int node = gwid;
    int beg = g_rowptr[node], end = g_rowptr[node + 1];
    if (beg == end) return;
    float4 Bb = *(const float4*)&g_ab[(size_t)node * 256 + HID + lane * 4];
    float4 bi = sb4[lane];
    Bb.x += bi.x; Bb.y += bi.y; Bb.z += bi.z; Bb.w += bi.w;
    float4 w0 = sWe[0][lane], w1 = sWe[1][lane], w2 = sWe[2][lane], w3 = sWe[3][lane];
    float4 v2 = sw24[lane];
    float bm2v = sbm2;
    int e = beg;
    for (; e + 3 < end; e += 4) {
        int2 se0 = __ldg(&g_se[e]);
        int2 se1 = __ldg(&g_se[e + 1]);
        int2 se2 = __ldg(&g_se[e + 2]);
        int2 se3 = __ldg(&g_se[e + 3]);
        float4 A0 = __ldg((const float4*)(g_ab + (size_t)se0.x * 256) + lane);
        float4 A1 = __ldg((const float4*)(g_ab + (size_t)se1.x * 256) + lane);
        float4 A2 = __ldg((const float4*)(g_ab + (size_t)se2.x * 256) + lane);
        float4 A3 = __ldg((const float4*)(g_ab + (size_t)se3.x * 256) + lane);
        float4 ev0 = __ldg((const float4*)&ea[(size_t)se0.y * 4]);
        float4 ev1 = __ldg((const float4*)&ea[(size_t)se1.y * 4]);
        float4 ev2 = __ldg((const float4*)&ea[(size_t)se2.y * 4]);
        float4 ev3 = __ldg((const float4*)&ea[(size_t)se3.y * 4]);
        float p0 = edge_dot(A0, Bb, ev0, w0, w1, w2, w3, v2);
        float p1 = edge_dot(A1, Bb, ev1, w0, w1, w2, w3, v2);
        float p2 = edge_dot(A2, Bb, ev2, w0, w1, w2, w3, v2);
        float p3 = edge_dot(A3, Bb, ev3, w0, w1, w2, w3, v2);
        #pragma unroll
        for (int off = 16; off; off >>= 1) {
            p0 += __shfl_xor_sync(0xffffffffu, p0, off);
            p1 += __shfl_xor_sync(0xffffffffu, p1, off);
            p2 += __shfl_xor_sync(0xffffffffu, p2, off);
            p3 += __shfl_xor_sync(0xffffffffu, p3, off);
        }
        if (lane == 0) out[se0.y] = 1.f / (1.f + __expf(-(p0 + bm2v)));
        if (lane == 1) out[se1.y] = 1.f / (1.f + __expf(-(p1 + bm2v)));
        if (lane == 2) out[se2.y] = 1.f / (1.f + __expf(-(p2 + bm2v)));
        if (lane == 3) out[se3.y] = 1.f / (1.f + __expf(-(p3 + bm2v)));
    }
    for (; e < end; e++) {
        int2 se0 = __ldg(&g_se[e]);
        float4 A0 = __ldg((const float4*)(g_ab + (size_t)se0.x * 256) + lane);
        float4 ev0 = __ldg((const float4*)&ea[(size_t)se0.y * 4]);
        float p0 = edge_dot(A0, Bb, ev0, w0, w1, w2, w3, v2);
        #pragma unroll
        for (int off = 16; off; off >>= 1)
            p0 += __shfl_xor_sync(0xffffffffu, p0, off);
        if (lane == 0) out[se0.y] = 1.f / (1.f + __expf(-(p0 + bm2v)));
    }
}

// ---------- launcher ----------
extern "C" void kernel_launch(void* const* d_in, const int* in_sizes, int n_in,
                              void* d_out, int out_size) {
    const float* x    = (const float*)d_in[0];
    const float* ea   = (const float*)d_in[1];
    const float* W1   = (const float*)d_in[2];
    const float* b1   = (const float*)d_in[3];
    const float* W2   = (const float*)d_in[4];
    const float* b2   = (const float*)d_in[5];
    const float* Wm1  = (const float*)d_in[6];
    const float* bm1  = (const float*)d_in[7];
    const float* Wm2  = (const float*)d_in[8];
    const float* bm2  = (const float*)d_in[9];
    const int*   ei   = (const int*)d_in[10];   // int32 (JAX x64 disabled)
    float* out = (float*)d_out;

    int n = in_sizes[0] / 5;          // 50000
    int E = in_sizes[10] / 2;         // 800000
    int nb = (n + 255) / 256;

    void *p_deg, *p_cur;
    float *p_t, *p_ab, *p_w2ab, *p_bab;
    cudaGetSymbolAddress(&p_deg, g_deg);
    cudaGetSymbolAddress(&p_cur, g_cur);
    cudaGetSymbolAddress((void**)&p_t, g_t);
    cudaGetSymbolAddress((void**)&p_ab, g_ab);
    cudaGetSymbolAddress((void**)&p_w2ab, g_w2ab);
    cudaGetSymbolAddress((void**)&p_bab, g_bab);

    // graph build — kernel launch #4 = fill_kernel (gets profiled by ncu -s 5)
    cudaMemsetAsync(p_deg, 0, (size_t)n * sizeof(int), 0);
    cudaMemsetAsync(p_cur, 0, (size_t)n * sizeof(int), 0);
    indeg_kernel<<<(E + 255) / 256, 256>>>(ei, E);
    disbsum_kernel<<<nb, 256>>>(n);
    rowptr2_kernel<<<nb, 256>>>(nb, n);
    fill_kernel<<<(E + 255) / 256, 256>>>(ei, E);

    // combined weights
    wcomb_kernel<<<128, 256>>>(W2, Wm1);
    wbias_kernel<<<1, 256>>>(b2, Wm1);

    // layer 1 fused: h1 = relu(agg(x) @ W1 + b1)
    aggx_gemm1_kernel<<<(n * 32 + 255) / 256, 256>>>(x, W1, b1, n);

    // layer 2 folded: u2 = agg(h1) ; [A|B] = u2 @ W2AB + bAB
    agg2_kernel<<<(n * 32 + 255) / 256, 256>>>(n);
    gemm256_kernel<<<(n + 63) / 64, 256>>>(p_t, p_w2ab, p_bab, p_ab, n);

    // per-edge head grouped by dst
    edge_kernel<<<(n * 32 + 255) / 256, 256>>>(ea, Wm1 + 256 * HID, bm1, Wm2, bm2, out, n);
}